// round 11
// baseline (speedup 1.0000x reference)
#include <cuda_runtime.h>
#include <cuda_fp16.h>
#include <cstdint>

#define BB 4
#define TT 2048
#define CC 1024
#define HH 16
#define DD 64
#define M_TOT (BB*TT)   // 8192

// Scratch (device globals: allocation-free rule)
__device__ __half g_xh[M_TOT*CC];        // x in fp16
__device__ __half g_wqkvh[CC*3*CC];      // W_qkv in fp16 [K][N]
__device__ __half g_woh[CC*CC];          // W_o in fp16 [K][N]
__device__ __half g_Q[BB*HH*TT*DD];      // [B,H,T,D] fp16
__device__ __half g_K[BB*HH*TT*DD];
__device__ __half g_V[BB*HH*TT*DD];
__device__ __half g_Att[M_TOT*CC];       // attention out [B,T,C] fp16

__device__ __forceinline__ void mma_f16(float& c0, float& c1, float& c2, float& c3,
                                        uint32_t a0, uint32_t a1, uint32_t a2, uint32_t a3,
                                        uint32_t b0, uint32_t b1)
{
    asm volatile(
        "mma.sync.aligned.m16n8k16.row.col.f32.f16.f16.f32 "
        "{%0,%1,%2,%3}, {%4,%5,%6,%7}, {%8,%9}, {%0,%1,%2,%3};"
        : "+f"(c0), "+f"(c1), "+f"(c2), "+f"(c3)
        : "r"(a0), "r"(a1), "r"(a2), "r"(a3), "r"(b0), "r"(b1));
}

// fp16-accumulator variant: D/C are 2 regs (4 halves)
__device__ __forceinline__ void mma_h16(uint32_t& c0, uint32_t& c1,
                                        uint32_t a0, uint32_t a1, uint32_t a2, uint32_t a3,
                                        uint32_t b0, uint32_t b1)
{
    asm volatile(
        "mma.sync.aligned.m16n8k16.row.col.f16.f16.f16.f16 "
        "{%0,%1}, {%2,%3,%4,%5}, {%6,%7}, {%0,%1};"
        : "+r"(c0), "+r"(c1)
        : "r"(a0), "r"(a1), "r"(a2), "r"(a3), "r"(b0), "r"(b1));
}

__device__ __forceinline__ void ldsm_x4(uint32_t& r0, uint32_t& r1, uint32_t& r2, uint32_t& r3,
                                        uint32_t addr)
{
    asm volatile("ldmatrix.sync.aligned.m8n8.x4.shared.b16 {%0,%1,%2,%3}, [%4];"
                 : "=r"(r0), "=r"(r1), "=r"(r2), "=r"(r3) : "r"(addr));
}

__device__ __forceinline__ void ldsm_x4_t(uint32_t& r0, uint32_t& r1, uint32_t& r2, uint32_t& r3,
                                          uint32_t addr)
{
    asm volatile("ldmatrix.sync.aligned.m8n8.x4.trans.shared.b16 {%0,%1,%2,%3}, [%4];"
                 : "=r"(r0), "=r"(r1), "=r"(r2), "=r"(r3) : "r"(addr));
}

__device__ __forceinline__ void cp_async16(void* smem_dst, const void* gmem_src) {
    uint32_t s = (uint32_t)__cvta_generic_to_shared(smem_dst);
    asm volatile("cp.async.cg.shared.global [%0], [%1], 16;" :: "r"(s), "l"(gmem_src));
}
#define CP_COMMIT() asm volatile("cp.async.commit_group;")
#define CP_WAIT1()  asm volatile("cp.async.wait_group 1;")
#define CP_WAIT0()  asm volatile("cp.async.wait_all;")

// pack two f32 -> half2 (lo, hi), then exp2 in fp16x2
__device__ __forceinline__ uint32_t exp2_pack(float lo, float hi) {
    uint32_t t, r;
    asm("cvt.rn.f16x2.f32 %0, %1, %2;" : "=r"(t) : "f"(hi), "f"(lo));
    asm("ex2.approx.f16x2 %0, %1;" : "=r"(r) : "r"(t));
    return r;
}

// ---------------------------------------------------------------------------
// fp32 -> fp16 conversion (one-time preprocess)
// ---------------------------------------------------------------------------
__global__ void cvt_half_kernel(const float* __restrict__ src, __half* __restrict__ dst, int n)
{
    int i = (blockIdx.x * blockDim.x + threadIdx.x) * 4;
    if (i < n) {
        float4 v = *(const float4*)&src[i];
        *(__half2*)&dst[i]     = __floats2half2_rn(v.x, v.y);
        *(__half2*)&dst[i + 2] = __floats2half2_rn(v.z, v.w);
    }
}

// ---------------------------------------------------------------------------
// fp16 GEMM, cp.async 3-stage pipeline, K-tile = 64.
// fp16 ACCUMULATORS in 32-K chunks, flushed to fp32 twice per stage.
// Tile 128x128x64, 256 threads (8 warps 4m x 2n), warp tile 32x64, 2 CTA/SM.
// mode 0: fp32 row-major write; mode 1: QKV fp16 scatter to [B,H,T,D]
// ---------------------------------------------------------------------------
#define GA_STH 72
#define GB_STH 136
#define GA_H (128*GA_STH)
#define GB_H (64*GB_STH)
#define GEMM_SMEM_BYTES ((3*GA_H + 3*GB_H) * 2)   // 107520

__global__ __launch_bounds__(256, 2)
void gemm_f16(const __half* __restrict__ A, const __half* __restrict__ W,
              const float* __restrict__ bias, float* __restrict__ Out,
              __half* __restrict__ Qp, __half* __restrict__ Kp, __half* __restrict__ Vp,
              int N, int mode)
{
    extern __shared__ __half smh[];
    __half* Asm[3] = { smh, smh + GA_H, smh + 2*GA_H };
    __half* Bsm[3] = { smh + 3*GA_H, smh + 3*GA_H + GB_H, smh + 3*GA_H + 2*GB_H };

    const int tid  = threadIdx.x;
    const int wid  = tid >> 5;
    const int lane = tid & 31;
    const int g    = lane >> 2;
    const int tig  = lane & 3;
    const int lr   = lane & 7;
    const int sel  = lane >> 3;
    const int wm   = wid & 3;
    const int wn   = wid >> 2;
    const int n0   = blockIdx.x * 128;
    const int m0   = blockIdx.y * 128;

    uint32_t smA[3], smB[3];
#pragma unroll
    for (int i = 0; i < 3; ++i) {
        smA[i] = (uint32_t)__cvta_generic_to_shared(Asm[i]);
        smB[i] = (uint32_t)__cvta_generic_to_shared(Bsm[i]);
    }
    const uint32_t aOff = ((wm * 32 + (sel & 1) * 8 + lr) * GA_STH + (sel >> 1) * 8) * 2;
    const uint32_t bOff = (((sel & 1) * 8 + lr) * GB_STH + wn * 64 + (sel >> 1) * 8) * 2;

    float acc[2][8][4];
#pragma unroll
    for (int mt = 0; mt < 2; ++mt)
#pragma unroll
        for (int nt = 0; nt < 8; ++nt)
#pragma unroll
            for (int q = 0; q < 4; ++q) acc[mt][nt][q] = 0.f;

    auto prefetch = [&](int s, int buf) {
        const int k0 = s * 64;
#pragma unroll
        for (int p = 0; p < 4; ++p) {
            int c  = tid + p * 256;
            int ra = c >> 3;
            int ka = (c & 7) * 8;
            cp_async16(&Asm[buf][ra * GA_STH + ka], &A[(m0 + ra) * 1024 + k0 + ka]);
            int rb = c >> 4;
            int nb = (c & 15) * 8;
            cp_async16(&Bsm[buf][rb * GB_STH + nb], &W[(k0 + rb) * N + n0 + nb]);
        }
    };

    prefetch(0, 0); CP_COMMIT();
    prefetch(1, 1); CP_COMMIT();

    for (int s = 0; s < 16; ++s) {
        CP_WAIT1();
        __syncthreads();
        if (s + 2 < 16) prefetch(s + 2, (s + 2) % 3);
        CP_COMMIT();

        const int buf = s % 3;
#pragma unroll
        for (int halfc = 0; halfc < 2; ++halfc) {   // 32-K chunks
            uint32_t hc[2][8][2];
#pragma unroll
            for (int mt = 0; mt < 2; ++mt)
#pragma unroll
                for (int nt = 0; nt < 8; ++nt) { hc[mt][nt][0] = 0u; hc[mt][nt][1] = 0u; }

#pragma unroll
            for (int ks2 = 0; ks2 < 2; ++ks2) {
                const int ks = halfc * 2 + ks2;
                uint32_t a[2][4];
#pragma unroll
                for (int mt = 0; mt < 2; ++mt)
                    ldsm_x4(a[mt][0], a[mt][1], a[mt][2], a[mt][3],
                            smA[buf] + aOff + (mt * 16 * GA_STH + ks * 16) * 2);
#pragma unroll
                for (int ph = 0; ph < 2; ++ph) {
                    uint32_t b0[4], b1[4];
                    ldsm_x4_t(b0[0], b0[1], b0[2], b0[3],
                              smB[buf] + bOff + (ks * 16 * GB_STH + (ph * 2 + 0) * 16) * 2);
                    ldsm_x4_t(b1[0], b1[1], b1[2], b1[3],
                              smB[buf] + bOff + (ks * 16 * GB_STH + (ph * 2 + 1) * 16) * 2);
#pragma unroll
                    for (int mt = 0; mt < 2; ++mt) {
                        mma_h16(hc[mt][4*ph+0][0], hc[mt][4*ph+0][1],
                                a[mt][0], a[mt][1], a[mt][2], a[mt][3], b0[0], b0[1]);
                        mma_h16(hc[mt][4*ph+1][0], hc[mt][4*ph+1][1],
                                a[mt][0], a[mt][1], a[mt][2], a[mt][3], b0[2], b0[3]);
                        mma_h16(hc[mt][4*ph+2][0], hc[mt][4*ph+2][1],
                                a[mt][0], a[mt][1], a[mt][2], a[mt][3], b1[0], b1[1]);
                        mma_h16(hc[mt][4*ph+3][0], hc[mt][4*ph+3][1],
                                a[mt][0], a[mt][1], a[mt][2], a[mt][3], b1[2], b1[3]);
                    }
                }
            }

            // flush fp16 chunk accumulators into fp32 master
#pragma unroll
            for (int mt = 0; mt < 2; ++mt)
#pragma unroll
                for (int nt = 0; nt < 8; ++nt) {
                    __half2 h0 = *(__half2*)&hc[mt][nt][0];
                    __half2 h1 = *(__half2*)&hc[mt][nt][1];
                    acc[mt][nt][0] += __low2float(h0);
                    acc[mt][nt][1] += __high2float(h0);
                    acc[mt][nt][2] += __low2float(h1);
                    acc[mt][nt][3] += __high2float(h1);
                }
        }
    }

    // epilogue
#pragma unroll
    for (int mt = 0; mt < 2; ++mt) {
#pragma unroll
        for (int nt = 0; nt < 8; ++nt) {
            int col = n0 + wn * 64 + nt * 8 + tig * 2;
            float2 bv = *(const float2*)&bias[col];
            int r0 = m0 + wm * 32 + mt * 16 + g;
#pragma unroll
            for (int h = 0; h < 2; ++h) {
                int row = r0 + h * 8;
                float vx = acc[mt][nt][h * 2 + 0] + bv.x;
                float vy = acc[mt][nt][h * 2 + 1] + bv.y;
                if (mode == 0) {
                    float2 v; v.x = vx; v.y = vy;
                    *(float2*)&Out[row * N + col] = v;
                } else {
                    int sec = col >> 10;
                    int rem = col & 1023;
                    int hh  = rem >> 6;
                    int d   = rem & 63;
                    int b   = row >> 11;
                    int t   = row & 2047;
                    __half* dst = (sec == 0) ? Qp : (sec == 1) ? Kp : Vp;
                    *(__half2*)&dst[(((b * HH + hh) * TT + t) << 6) + d] =
                        __floats2half2_rn(vx, vy);
                }
            }
        }
    }
}

// ---------------------------------------------------------------------------
// Flash attention (R9, unchanged): static-max exp2/fp16 softmax, mma row-sums,
// 3-stage KV pipeline, balanced pairing (bx, 15-bx).
// ---------------------------------------------------------------------------
#define KV_STH 72
#define KV_H (64*KV_STH)
#define ATTN_SMEM_BYTES (6*KV_H*2)              // 55296
#define MASKV (-30.0f)

__global__ __launch_bounds__(256, 2)
void attn_f16(const __half* __restrict__ Q, const __half* __restrict__ K,
              const __half* __restrict__ V, __half* __restrict__ O)
{
    extern __shared__ __half smh[];
    __half* Kb[3] = { smh,        smh + 2*KV_H, smh + 4*KV_H };
    __half* Vb[3] = { smh + KV_H, smh + 3*KV_H, smh + 5*KV_H };

    const int tid  = threadIdx.x;
    const int wid  = tid >> 5;
    const int lane = tid & 31;
    const int g    = lane >> 2;
    const int tig  = lane & 3;
    const int lr   = lane & 7;
    const int sel  = lane >> 3;
    const int wq   = wid * 16;
    const int head = blockIdx.y;
    const int b    = blockIdx.z;

    const int base = (b * HH + head) * TT * DD;
    const __half* Qg = Q + base;
    const __half* Kg = K + base;
    const __half* Vg = V + base;

    uint32_t smK[3], smV[3];
#pragma unroll
    for (int i = 0; i < 3; ++i) {
        smK[i] = (uint32_t)__cvta_generic_to_shared(Kb[i]);
        smV[i] = (uint32_t)__cvta_generic_to_shared(Vb[i]);
    }
    const uint32_t kOff = (((sel >> 1) * 8 + lr) * KV_STH + (sel & 1) * 8) * 2;
    const uint32_t vOff = (((sel & 1) * 8 + lr) * KV_STH + (sel >> 1) * 8) * 2;
    const uint32_t qOff = ((wq + (sel & 1) * 8 + lr) * KV_STH + (sel >> 1) * 8) * 2;

    const uint32_t onesb = ((lane >> 2) == 0) ? 0x3C003C00u : 0u;

    auto prefetch = [&](int jt, int buf) {
        const int k0 = jt * 64;
#pragma unroll
        for (int p = 0; p < 2; ++p) {
            int c  = tid + p * 256;
            int r  = c >> 3;
            int dc = (c & 7) * 8;
            cp_async16(&Kb[buf][r * KV_STH + dc], &Kg[(k0 + r) * DD + dc]);
            cp_async16(&Vb[buf][r * KV_STH + dc], &Vg[(k0 + r) * DD + dc]);
        }
    };

#pragma unroll 1
    for (int pass = 0; pass < 2; ++pass) {
        const int qb = pass == 0 ? (int)blockIdx.x : 15 - (int)blockIdx.x;
        const int q0 = qb * 128;

        CP_WAIT0();
        __syncthreads();
        {
            const __half2 sc2 = __float2half2_rn(0.1803368801f);  // log2(e)/8
#pragma unroll
            for (int p = 0; p < 16; ++p) {
                int idx = tid + p * 256;
                int r   = idx >> 5;
                int d2  = (idx & 31);
                __half2 v = *(const __half2*)&Qg[(q0 + r) * DD + d2 * 2];
                *(__half2*)&smh[r * KV_STH + d2 * 2] = __hmul2(v, sc2);
            }
            __syncthreads();
        }
        uint32_t qa[4][4];
        {
            uint32_t qBase = (uint32_t)__cvta_generic_to_shared(smh);
#pragma unroll
            for (int ks = 0; ks < 4; ++ks)
                ldsm_x4(qa[ks][0], qa[ks][1], qa[ks][2], qa[ks][3],
                        qBase + qOff + ks * 32);
            __syncthreads();
        }

        float o[8][4];
#pragma unroll
        for (int nt = 0; nt < 8; ++nt)
#pragma unroll
            for (int q = 0; q < 4; ++q) o[nt][q] = 0.f;
        float lsum[4] = {0.f, 0.f, 0.f, 0.f};

        const int row0 = q0 + wq + g;
        const int row1 = row0 + 8;
        const int n_tiles = 2 * (qb + 1);

        prefetch(0, 0); CP_COMMIT();
        prefetch(1, 1); CP_COMMIT();

        for (int jt = 0; jt < n_tiles; ++jt) {
            const int k0 = jt * 64;
            CP_WAIT1();
            __syncthreads();
            if (jt + 2 < n_tiles) prefetch(jt + 2, (jt + 2) % 3);
            CP_COMMIT();

            const int buf = jt % 3;

            float sc[8][4];
#pragma unroll
            for (int nt = 0; nt < 8; ++nt)
#pragma unroll
                for (int q = 0; q < 4; ++q) sc[nt][q] = 0.f;

#pragma unroll
            for (int ks = 0; ks < 4; ++ks) {
#pragma unroll
                for (int ph = 0; ph < 2; ++ph) {
                    uint32_t b0[4], b1[4];
                    ldsm_x4(b0[0], b0[1], b0[2], b0[3],
                            smK[buf] + kOff + ((ph * 2 + 0) * 16 * KV_STH + ks * 16) * 2);
                    ldsm_x4(b1[0], b1[1], b1[2], b1[3],
                            smK[buf] + kOff + ((ph * 2 + 1) * 16 * KV_STH + ks * 16) * 2);
                    mma_f16(sc[4*ph+0][0], sc[4*ph+0][1], sc[4*ph+0][2], sc[4*ph+0][3],
                            qa[ks][0], qa[ks][1], qa[ks][2], qa[ks][3], b0[0], b0[1]);
                    mma_f16(sc[4*ph+1][0], sc[4*ph+1][1], sc[4*ph+1][2], sc[4*ph+1][3],
                            qa[ks][0], qa[ks][1], qa[ks][2], qa[ks][3], b0[2], b0[3]);
                    mma_f16(sc[4*ph+2][0], sc[4*ph+2][1], sc[4*ph+2][2], sc[4*ph+2][3],
                            qa[ks][0], qa[ks][1], qa[ks][2], qa[ks][3], b1[0], b1[1]);
                    mma_f16(sc[4*ph+3][0], sc[4*ph+3][1], sc[4*ph+3][2], sc[4*ph+3][3],
                            qa[ks][0], qa[ks][1], qa[ks][2], qa[ks][3], b1[2], b1[3]);
                }
            }

            if (k0 + 63 > row0) {
#pragma unroll
                for (int nt = 0; nt < 8; ++nt) {
                    int c0 = k0 + nt * 8 + tig * 2;
                    int c1 = c0 + 1;
                    if (c0 > row0) sc[nt][0] = MASKV;
                    if (c1 > row0) sc[nt][1] = MASKV;
                    if (c0 > row1) sc[nt][2] = MASKV;
                    if (c1 > row1) sc[nt][3] = MASKV;
                }
            }

            uint32_t ph16[8][2];
#pragma unroll
            for (int nt = 0; nt < 8; ++nt) {
                ph16[nt][0] = exp2_pack(sc[nt][0], sc[nt][1]);
                ph16[nt][1] = exp2_pack(sc[nt][2], sc[nt][3]);
            }

#pragma unroll
            for (int c = 0; c < 4; ++c) {
                uint32_t a0 = ph16[2*c    ][0];
                uint32_t a1 = ph16[2*c    ][1];
                uint32_t a2 = ph16[2*c + 1][0];
                uint32_t a3 = ph16[2*c + 1][1];
                mma_f16(lsum[0], lsum[1], lsum[2], lsum[3],
                        a0, a1, a2, a3, onesb, onesb);
#pragma unroll
                for (int ph = 0; ph < 2; ++ph) {
                    uint32_t b0[4], b1[4];
                    ldsm_x4_t(b0[0], b0[1], b0[2], b0[3],
                              smV[buf] + vOff + (c * 16 * KV_STH + (ph * 2 + 0) * 16) * 2);
                    ldsm_x4_t(b1[0], b1[1], b1[2], b1[3],
                              smV[buf] + vOff + (c * 16 * KV_STH + (ph * 2 + 1) * 16) * 2);
                    mma_f16(o[4*ph+0][0], o[4*ph+0][1], o[4*ph+0][2], o[4*ph+0][3],
                            a0, a1, a2, a3, b0[0], b0[1]);
                    mma_f16(o[4*ph+1][0], o[4*ph+1][1], o[4*ph+1][2], o[4*ph+1][3],
                            a0, a1, a2, a3, b0[2], b0[3]);
                    mma_f16(o[4*ph+2][0], o[4*ph+2][1], o[4*ph+2][2], o[4*ph+2][3],
                            a0, a1, a2, a3, b1[0], b1[1]);
                    mma_f16(o[4*ph+3][0], o[4*ph+3][1], o[4*ph+3][2], o[4*ph+3][3],
                            a0, a1, a2, a3, b1[2], b1[3]);
                }
            }
        }

        int qlead = lane & ~3;
        float l0 = __shfl_sync(0xffffffffu, lsum[0], qlead);
        float l1 = __shfl_sync(0xffffffffu, lsum[2], qlead);
        float inv0 = 1.f / l0;
        float inv1 = 1.f / l1;
#pragma unroll
        for (int nt = 0; nt < 8; ++nt) {
            int d = head * DD + nt * 8 + tig * 2;
            *(__half2*)&O[(b * TT + row0) * CC + d] =
                __floats2half2_rn(o[nt][0] * inv0, o[nt][1] * inv0);
            *(__half2*)&O[(b * TT + row1) * CC + d] =
                __floats2half2_rn(o[nt][2] * inv1, o[nt][3] * inv1);
        }
    }
}

// ---------------------------------------------------------------------------
extern "C" void kernel_launch(void* const* d_in, const int* in_sizes, int n_in,
                              void* d_out, int out_size)
{
    const float* x    = (const float*)d_in[0];  // [4,2048,1024]
    const float* Wqkv = (const float*)d_in[1];  // [1024,3072]
    const float* bqkv = (const float*)d_in[2];  // [3072]
    const float* Wo   = (const float*)d_in[3];  // [1024,1024]
    const float* bo   = (const float*)d_in[4];  // [1024]
    float* out = (float*)d_out;                 // [4,2048,1024]

    __half *xh, *wqkvh, *woh, *gQ, *gK, *gV, *gAtt;
    cudaGetSymbolAddress((void**)&xh,    g_xh);
    cudaGetSymbolAddress((void**)&wqkvh, g_wqkvh);
    cudaGetSymbolAddress((void**)&woh,   g_woh);
    cudaGetSymbolAddress((void**)&gQ,    g_Q);
    cudaGetSymbolAddress((void**)&gK,    g_K);
    cudaGetSymbolAddress((void**)&gV,    g_V);
    cudaGetSymbolAddress((void**)&gAtt,  g_Att);

    cudaFuncSetAttribute(gemm_f16, cudaFuncAttributeMaxDynamicSharedMemorySize,
                         GEMM_SMEM_BYTES);
    cudaFuncSetAttribute(attn_f16, cudaFuncAttributeMaxDynamicSharedMemorySize,
                         ATTN_SMEM_BYTES);

    // 0) convert inputs to fp16
    cvt_half_kernel<<<(M_TOT*CC/4 + 255)/256, 256>>>(x, xh, M_TOT*CC);
    cvt_half_kernel<<<(CC*3*CC/4 + 255)/256, 256>>>(Wqkv, wqkvh, CC*3*CC);
    cvt_half_kernel<<<(CC*CC/4 + 255)/256, 256>>>(Wo, woh, CC*CC);

    // 1) QKV projection + fp16 scatter to [B,H,T,D]
    gemm_f16<<<dim3(3072 / 128, M_TOT / 128), 256, GEMM_SMEM_BYTES>>>(
        xh, wqkvh, bqkv, nullptr, gQ, gK, gV, 3072, 1);

    // 2) causal flash attention -> fp16 [B,T,C] (paired q-blocks, balanced)
    attn_f16<<<dim3(8, HH, BB), 256, ATTN_SMEM_BYTES>>>(gQ, gK, gV, gAtt);

    // 3) output projection (fp16 in, fp32 out)
    gemm_f16<<<dim3(1024 / 128, M_TOT / 128), 256, GEMM_SMEM_BYTES>>>(
        gAtt, woh, bo, out, nullptr, nullptr, nullptr, 1024, 0);
}

// round 12
// speedup vs baseline: 1.1300x; 1.1300x over previous
#include <cuda_runtime.h>
#include <cuda_fp16.h>
#include <cstdint>

#define BB 4
#define TT 2048
#define CC 1024
#define HH 16
#define DD 64
#define M_TOT (BB*TT)   // 8192

// Scratch (device globals: allocation-free rule)
__device__ __half g_xh[M_TOT*CC];        // x in fp16
__device__ __half g_wqkvh[CC*3*CC];      // W_qkv in fp16 [K][N]
__device__ __half g_woh[CC*CC];          // W_o in fp16 [K][N]
__device__ __half g_Q[BB*HH*TT*DD];      // [B,H,T,D] fp16
__device__ __half g_K[BB*HH*TT*DD];
__device__ __half g_V[BB*HH*TT*DD];
__device__ __half g_Att[M_TOT*CC];       // attention out [B,T,C] fp16

__device__ __forceinline__ void mma_f16(float& c0, float& c1, float& c2, float& c3,
                                        uint32_t a0, uint32_t a1, uint32_t a2, uint32_t a3,
                                        uint32_t b0, uint32_t b1)
{
    asm volatile(
        "mma.sync.aligned.m16n8k16.row.col.f32.f16.f16.f32 "
        "{%0,%1,%2,%3}, {%4,%5,%6,%7}, {%8,%9}, {%0,%1,%2,%3};"
        : "+f"(c0), "+f"(c1), "+f"(c2), "+f"(c3)
        : "r"(a0), "r"(a1), "r"(a2), "r"(a3), "r"(b0), "r"(b1));
}

__device__ __forceinline__ void ldsm_x4(uint32_t& r0, uint32_t& r1, uint32_t& r2, uint32_t& r3,
                                        uint32_t addr)
{
    asm volatile("ldmatrix.sync.aligned.m8n8.x4.shared.b16 {%0,%1,%2,%3}, [%4];"
                 : "=r"(r0), "=r"(r1), "=r"(r2), "=r"(r3) : "r"(addr));
}

__device__ __forceinline__ void ldsm_x4_t(uint32_t& r0, uint32_t& r1, uint32_t& r2, uint32_t& r3,
                                          uint32_t addr)
{
    asm volatile("ldmatrix.sync.aligned.m8n8.x4.trans.shared.b16 {%0,%1,%2,%3}, [%4];"
                 : "=r"(r0), "=r"(r1), "=r"(r2), "=r"(r3) : "r"(addr));
}

__device__ __forceinline__ void cp_async16(void* smem_dst, const void* gmem_src) {
    uint32_t s = (uint32_t)__cvta_generic_to_shared(smem_dst);
    asm volatile("cp.async.cg.shared.global [%0], [%1], 16;" :: "r"(s), "l"(gmem_src));
}
#define CP_COMMIT() asm volatile("cp.async.commit_group;")
#define CP_WAIT1()  asm volatile("cp.async.wait_group 1;")
#define CP_WAIT2()  asm volatile("cp.async.wait_group 2;")
#define CP_WAIT0()  asm volatile("cp.async.wait_all;")

// pack two f32 -> half2 (lo, hi), then exp2 in fp16x2
__device__ __forceinline__ uint32_t exp2_pack(float lo, float hi) {
    uint32_t t, r;
    asm("cvt.rn.f16x2.f32 %0, %1, %2;" : "=r"(t) : "f"(hi), "f"(lo));
    asm("ex2.approx.f16x2 %0, %1;" : "=r"(r) : "r"(t));
    return r;
}

// ---------------------------------------------------------------------------
// fp32 -> fp16 conversion (one-time preprocess)
// ---------------------------------------------------------------------------
__global__ void cvt_half_kernel(const float* __restrict__ src, __half* __restrict__ dst, int n)
{
    int i = (blockIdx.x * blockDim.x + threadIdx.x) * 4;
    if (i < n) {
        float4 v = *(const float4*)&src[i];
        *(__half2*)&dst[i]     = __floats2half2_rn(v.x, v.y);
        *(__half2*)&dst[i + 2] = __floats2half2_rn(v.z, v.w);
    }
}

// ---------------------------------------------------------------------------
// fp16 GEMM: CTA 256x128, 512 threads (16 warps 4m x 4n), warp tile 64x32.
// K-stage 64; 4 smem buffers; barrier window = 2 stages (32 mma/warp/window).
// fp32 accumulate. mode 0: fp32 write; mode 1: QKV fp16 scatter.
// Smem: 4 x (A[256][72] + B[64][136]) halves = 217,088 B. 1 CTA/SM.
// ---------------------------------------------------------------------------
#define GA_STH 72
#define GB_STH 136
#define GA_H (256*GA_STH)        // 18432 halves / buffer
#define GB_H (64*GB_STH)         // 8704 halves / buffer
#define GEMM_SMEM_BYTES (4*(GA_H + GB_H)*2)   // 217088

__global__ __launch_bounds__(512, 1)
void gemm_f16(const __half* __restrict__ A, const __half* __restrict__ W,
              const float* __restrict__ bias, float* __restrict__ Out,
              __half* __restrict__ Qp, __half* __restrict__ Kp, __half* __restrict__ Vp,
              int N, int mode)
{
    extern __shared__ __half smh[];
    __half* Asm[4]; __half* Bsm[4];
#pragma unroll
    for (int i = 0; i < 4; ++i) {
        Asm[i] = smh + i * (GA_H + GB_H);
        Bsm[i] = Asm[i] + GA_H;
    }

    const int tid  = threadIdx.x;
    const int wid  = tid >> 5;
    const int lane = tid & 31;
    const int g    = lane >> 2;
    const int tig  = lane & 3;
    const int lr   = lane & 7;
    const int sel  = lane >> 3;
    const int wm   = wid & 3;          // m offset wm*64
    const int wn   = wid >> 2;         // n offset wn*32
    const int n0   = blockIdx.x * 128;
    const int m0   = blockIdx.y * 256;

    uint32_t smA[4], smB[4];
#pragma unroll
    for (int i = 0; i < 4; ++i) {
        smA[i] = (uint32_t)__cvta_generic_to_shared(Asm[i]);
        smB[i] = (uint32_t)__cvta_generic_to_shared(Bsm[i]);
    }
    const uint32_t aOff = ((wm * 64 + (sel & 1) * 8 + lr) * GA_STH + (sel >> 1) * 8) * 2;
    const uint32_t bOff = (((sel & 1) * 8 + lr) * GB_STH + wn * 32 + (sel >> 1) * 8) * 2;

    float acc[4][4][4];
#pragma unroll
    for (int mt = 0; mt < 4; ++mt)
#pragma unroll
        for (int nt = 0; nt < 4; ++nt)
#pragma unroll
            for (int q = 0; q < 4; ++q) acc[mt][nt][q] = 0.f;

    auto prefetch = [&](int s, int buf) {
        const int k0 = s * 64;
        // A: 256 rows x 64 halves = 2048 16B chunks -> 4/thread
#pragma unroll
        for (int p = 0; p < 4; ++p) {
            int c  = tid + p * 512;
            int ra = c >> 3;
            int ka = (c & 7) * 8;
            cp_async16(&Asm[buf][ra * GA_STH + ka], &A[(m0 + ra) * 1024 + k0 + ka]);
        }
        // B: 64 rows x 128 halves = 1024 chunks -> 2/thread
#pragma unroll
        for (int p = 0; p < 2; ++p) {
            int c  = tid + p * 512;
            int rb = c >> 4;
            int nb = (c & 15) * 8;
            cp_async16(&Bsm[buf][rb * GB_STH + nb], &W[(k0 + rb) * N + n0 + nb]);
        }
    };

    auto compute_stage = [&](int buf) {
#pragma unroll
        for (int ks = 0; ks < 4; ++ks) {
            uint32_t a[4][4];
#pragma unroll
            for (int mt = 0; mt < 4; ++mt)
                ldsm_x4(a[mt][0], a[mt][1], a[mt][2], a[mt][3],
                        smA[buf] + aOff + (mt * 16 * GA_STH + ks * 16) * 2);
#pragma unroll
            for (int p = 0; p < 2; ++p) {
                uint32_t b0, b1, b2, b3;
                ldsm_x4_t(b0, b1, b2, b3,
                          smB[buf] + bOff + (ks * 16 * GB_STH + p * 16) * 2);
#pragma unroll
                for (int mt = 0; mt < 4; ++mt) {
                    mma_f16(acc[mt][2*p][0], acc[mt][2*p][1], acc[mt][2*p][2], acc[mt][2*p][3],
                            a[mt][0], a[mt][1], a[mt][2], a[mt][3], b0, b1);
                    mma_f16(acc[mt][2*p+1][0], acc[mt][2*p+1][1], acc[mt][2*p+1][2], acc[mt][2*p+1][3],
                            a[mt][0], a[mt][1], a[mt][2], a[mt][3], b2, b3);
                }
            }
        }
    };

    prefetch(0, 0); CP_COMMIT();
    prefetch(1, 1); CP_COMMIT();

    for (int w = 0; w < 8; ++w) {
        const int s0 = 2 * w;
        // prefetch next window into the buffers computed last window (freed by
        // the trailing barrier of that window); empty commits keep group math uniform
        if (s0 + 2 < 16) prefetch(s0 + 2, (s0 + 2) & 3);
        CP_COMMIT();
        if (s0 + 3 < 16) prefetch(s0 + 3, (s0 + 3) & 3);
        CP_COMMIT();
        CP_WAIT2();          // stages s0, s0+1 landed (the 2 just-committed remain)
        __syncthreads();     // all threads see landed data
        compute_stage(s0 & 3);
        compute_stage((s0 + 1) & 3);
        __syncthreads();     // compute done before next window's prefetch overwrites
    }

    // epilogue
#pragma unroll
    for (int mt = 0; mt < 4; ++mt) {
#pragma unroll
        for (int nt = 0; nt < 4; ++nt) {
            int col = n0 + wn * 32 + nt * 8 + tig * 2;
            float2 bv = *(const float2*)&bias[col];
            int r0 = m0 + wm * 64 + mt * 16 + g;
#pragma unroll
            for (int h = 0; h < 2; ++h) {
                int row = r0 + h * 8;
                float vx = acc[mt][nt][h * 2 + 0] + bv.x;
                float vy = acc[mt][nt][h * 2 + 1] + bv.y;
                if (mode == 0) {
                    float2 v; v.x = vx; v.y = vy;
                    *(float2*)&Out[row * N + col] = v;
                } else {
                    int sec = col >> 10;           // 0:Q 1:K 2:V
                    int rem = col & 1023;
                    int hh  = rem >> 6;
                    int d   = rem & 63;
                    int b   = row >> 11;
                    int t   = row & 2047;
                    __half* dst = (sec == 0) ? Qp : (sec == 1) ? Kp : Vp;
                    *(__half2*)&dst[(((b * HH + hh) * TT + t) << 6) + d] =
                        __floats2half2_rn(vx, vy);
                }
            }
        }
    }
}

// ---------------------------------------------------------------------------
// Flash attention (R9, unchanged): static-max exp2/fp16 softmax, mma row-sums,
// 3-stage KV pipeline, balanced pairing (bx, 15-bx).
// ---------------------------------------------------------------------------
#define KV_STH 72
#define KV_H (64*KV_STH)
#define ATTN_SMEM_BYTES (6*KV_H*2)              // 55296
#define MASKV (-30.0f)

__global__ __launch_bounds__(256, 2)
void attn_f16(const __half* __restrict__ Q, const __half* __restrict__ K,
              const __half* __restrict__ V, __half* __restrict__ O)
{
    extern __shared__ __half smh[];
    __half* Kb[3] = { smh,        smh + 2*KV_H, smh + 4*KV_H };
    __half* Vb[3] = { smh + KV_H, smh + 3*KV_H, smh + 5*KV_H };

    const int tid  = threadIdx.x;
    const int wid  = tid >> 5;
    const int lane = tid & 31;
    const int g    = lane >> 2;
    const int tig  = lane & 3;
    const int lr   = lane & 7;
    const int sel  = lane >> 3;
    const int wq   = wid * 16;
    const int head = blockIdx.y;
    const int b    = blockIdx.z;

    const int base = (b * HH + head) * TT * DD;
    const __half* Qg = Q + base;
    const __half* Kg = K + base;
    const __half* Vg = V + base;

    uint32_t smK[3], smV[3];
#pragma unroll
    for (int i = 0; i < 3; ++i) {
        smK[i] = (uint32_t)__cvta_generic_to_shared(Kb[i]);
        smV[i] = (uint32_t)__cvta_generic_to_shared(Vb[i]);
    }
    const uint32_t kOff = (((sel >> 1) * 8 + lr) * KV_STH + (sel & 1) * 8) * 2;
    const uint32_t vOff = (((sel & 1) * 8 + lr) * KV_STH + (sel >> 1) * 8) * 2;
    const uint32_t qOff = ((wq + (sel & 1) * 8 + lr) * KV_STH + (sel >> 1) * 8) * 2;

    const uint32_t onesb = ((lane >> 2) == 0) ? 0x3C003C00u : 0u;

    auto prefetch = [&](int jt, int buf) {
        const int k0 = jt * 64;
#pragma unroll
        for (int p = 0; p < 2; ++p) {
            int c  = tid + p * 256;
            int r  = c >> 3;
            int dc = (c & 7) * 8;
            cp_async16(&Kb[buf][r * KV_STH + dc], &Kg[(k0 + r) * DD + dc]);
            cp_async16(&Vb[buf][r * KV_STH + dc], &Vg[(k0 + r) * DD + dc]);
        }
    };

#pragma unroll 1
    for (int pass = 0; pass < 2; ++pass) {
        const int qb = pass == 0 ? (int)blockIdx.x : 15 - (int)blockIdx.x;
        const int q0 = qb * 128;

        CP_WAIT0();
        __syncthreads();
        {
            const __half2 sc2 = __float2half2_rn(0.1803368801f);  // log2(e)/8
#pragma unroll
            for (int p = 0; p < 16; ++p) {
                int idx = tid + p * 256;
                int r   = idx >> 5;
                int d2  = (idx & 31);
                __half2 v = *(const __half2*)&Qg[(q0 + r) * DD + d2 * 2];
                *(__half2*)&smh[r * KV_STH + d2 * 2] = __hmul2(v, sc2);
            }
            __syncthreads();
        }
        uint32_t qa[4][4];
        {
            uint32_t qBase = (uint32_t)__cvta_generic_to_shared(smh);
#pragma unroll
            for (int ks = 0; ks < 4; ++ks)
                ldsm_x4(qa[ks][0], qa[ks][1], qa[ks][2], qa[ks][3],
                        qBase + qOff + ks * 32);
            __syncthreads();
        }

        float o[8][4];
#pragma unroll
        for (int nt = 0; nt < 8; ++nt)
#pragma unroll
            for (int q = 0; q < 4; ++q) o[nt][q] = 0.f;
        float lsum[4] = {0.f, 0.f, 0.f, 0.f};

        const int row0 = q0 + wq + g;
        const int row1 = row0 + 8;
        const int n_tiles = 2 * (qb + 1);

        prefetch(0, 0); CP_COMMIT();
        prefetch(1, 1); CP_COMMIT();

        for (int jt = 0; jt < n_tiles; ++jt) {
            const int k0 = jt * 64;
            CP_WAIT1();
            __syncthreads();
            if (jt + 2 < n_tiles) prefetch(jt + 2, (jt + 2) % 3);
            CP_COMMIT();

            const int buf = jt % 3;

            float sc[8][4];
#pragma unroll
            for (int nt = 0; nt < 8; ++nt)
#pragma unroll
                for (int q = 0; q < 4; ++q) sc[nt][q] = 0.f;

#pragma unroll
            for (int ks = 0; ks < 4; ++ks) {
#pragma unroll
                for (int ph = 0; ph < 2; ++ph) {
                    uint32_t b0[4], b1[4];
                    ldsm_x4(b0[0], b0[1], b0[2], b0[3],
                            smK[buf] + kOff + ((ph * 2 + 0) * 16 * KV_STH + ks * 16) * 2);
                    ldsm_x4(b1[0], b1[1], b1[2], b1[3],
                            smK[buf] + kOff + ((ph * 2 + 1) * 16 * KV_STH + ks * 16) * 2);
                    mma_f16(sc[4*ph+0][0], sc[4*ph+0][1], sc[4*ph+0][2], sc[4*ph+0][3],
                            qa[ks][0], qa[ks][1], qa[ks][2], qa[ks][3], b0[0], b0[1]);
                    mma_f16(sc[4*ph+1][0], sc[4*ph+1][1], sc[4*ph+1][2], sc[4*ph+1][3],
                            qa[ks][0], qa[ks][1], qa[ks][2], qa[ks][3], b0[2], b0[3]);
                    mma_f16(sc[4*ph+2][0], sc[4*ph+2][1], sc[4*ph+2][2], sc[4*ph+2][3],
                            qa[ks][0], qa[ks][1], qa[ks][2], qa[ks][3], b1[0], b1[1]);
                    mma_f16(sc[4*ph+3][0], sc[4*ph+3][1], sc[4*ph+3][2], sc[4*ph+3][3],
                            qa[ks][0], qa[ks][1], qa[ks][2], qa[ks][3], b1[2], b1[3]);
                }
            }

            if (k0 + 63 > row0) {
#pragma unroll
                for (int nt = 0; nt < 8; ++nt) {
                    int c0 = k0 + nt * 8 + tig * 2;
                    int c1 = c0 + 1;
                    if (c0 > row0) sc[nt][0] = MASKV;
                    if (c1 > row0) sc[nt][1] = MASKV;
                    if (c0 > row1) sc[nt][2] = MASKV;
                    if (c1 > row1) sc[nt][3] = MASKV;
                }
            }

            uint32_t ph16[8][2];
#pragma unroll
            for (int nt = 0; nt < 8; ++nt) {
                ph16[nt][0] = exp2_pack(sc[nt][0], sc[nt][1]);
                ph16[nt][1] = exp2_pack(sc[nt][2], sc[nt][3]);
            }

#pragma unroll
            for (int c = 0; c < 4; ++c) {
                uint32_t a0 = ph16[2*c    ][0];
                uint32_t a1 = ph16[2*c    ][1];
                uint32_t a2 = ph16[2*c + 1][0];
                uint32_t a3 = ph16[2*c + 1][1];
                mma_f16(lsum[0], lsum[1], lsum[2], lsum[3],
                        a0, a1, a2, a3, onesb, onesb);
#pragma unroll
                for (int ph = 0; ph < 2; ++ph) {
                    uint32_t b0[4], b1[4];
                    ldsm_x4_t(b0[0], b0[1], b0[2], b0[3],
                              smV[buf] + vOff + (c * 16 * KV_STH + (ph * 2 + 0) * 16) * 2);
                    ldsm_x4_t(b1[0], b1[1], b1[2], b1[3],
                              smV[buf] + vOff + (c * 16 * KV_STH + (ph * 2 + 1) * 16) * 2);
                    mma_f16(o[4*ph+0][0], o[4*ph+0][1], o[4*ph+0][2], o[4*ph+0][3],
                            a0, a1, a2, a3, b0[0], b0[1]);
                    mma_f16(o[4*ph+1][0], o[4*ph+1][1], o[4*ph+1][2], o[4*ph+1][3],
                            a0, a1, a2, a3, b0[2], b0[3]);
                    mma_f16(o[4*ph+2][0], o[4*ph+2][1], o[4*ph+2][2], o[4*ph+2][3],
                            a0, a1, a2, a3, b1[0], b1[1]);
                    mma_f16(o[4*ph+3][0], o[4*ph+3][1], o[4*ph+3][2], o[4*ph+3][3],
                            a0, a1, a2, a3, b1[2], b1[3]);
                }
            }
        }

        int qlead = lane & ~3;
        float l0 = __shfl_sync(0xffffffffu, lsum[0], qlead);
        float l1 = __shfl_sync(0xffffffffu, lsum[2], qlead);
        float inv0 = 1.f / l0;
        float inv1 = 1.f / l1;
#pragma unroll
        for (int nt = 0; nt < 8; ++nt) {
            int d = head * DD + nt * 8 + tig * 2;
            *(__half2*)&O[(b * TT + row0) * CC + d] =
                __floats2half2_rn(o[nt][0] * inv0, o[nt][1] * inv0);
            *(__half2*)&O[(b * TT + row1) * CC + d] =
                __floats2half2_rn(o[nt][2] * inv1, o[nt][3] * inv1);
        }
    }
}

// ---------------------------------------------------------------------------
extern "C" void kernel_launch(void* const* d_in, const int* in_sizes, int n_in,
                              void* d_out, int out_size)
{
    const float* x    = (const float*)d_in[0];  // [4,2048,1024]
    const float* Wqkv = (const float*)d_in[1];  // [1024,3072]
    const float* bqkv = (const float*)d_in[2];  // [3072]
    const float* Wo   = (const float*)d_in[3];  // [1024,1024]
    const float* bo   = (const float*)d_in[4];  // [1024]
    float* out = (float*)d_out;                 // [4,2048,1024]

    __half *xh, *wqkvh, *woh, *gQ, *gK, *gV, *gAtt;
    cudaGetSymbolAddress((void**)&xh,    g_xh);
    cudaGetSymbolAddress((void**)&wqkvh, g_wqkvh);
    cudaGetSymbolAddress((void**)&woh,   g_woh);
    cudaGetSymbolAddress((void**)&gQ,    g_Q);
    cudaGetSymbolAddress((void**)&gK,    g_K);
    cudaGetSymbolAddress((void**)&gV,    g_V);
    cudaGetSymbolAddress((void**)&gAtt,  g_Att);

    cudaFuncSetAttribute(gemm_f16, cudaFuncAttributeMaxDynamicSharedMemorySize,
                         GEMM_SMEM_BYTES);
    cudaFuncSetAttribute(attn_f16, cudaFuncAttributeMaxDynamicSharedMemorySize,
                         ATTN_SMEM_BYTES);

    // 0) convert inputs to fp16
    cvt_half_kernel<<<(M_TOT*CC/4 + 255)/256, 256>>>(x, xh, M_TOT*CC);
    cvt_half_kernel<<<(CC*3*CC/4 + 255)/256, 256>>>(Wqkv, wqkvh, CC*3*CC);
    cvt_half_kernel<<<(CC*CC/4 + 255)/256, 256>>>(Wo, woh, CC*CC);

    // 1) QKV projection + fp16 scatter to [B,H,T,D]
    gemm_f16<<<dim3(3072 / 128, M_TOT / 256), 512, GEMM_SMEM_BYTES>>>(
        xh, wqkvh, bqkv, nullptr, gQ, gK, gV, 3072, 1);

    // 2) causal flash attention -> fp16 [B,T,C] (paired q-blocks, balanced)
    attn_f16<<<dim3(8, HH, BB), 256, ATTN_SMEM_BYTES>>>(gQ, gK, gV, gAtt);

    // 3) output projection (fp16 in, fp32 out)
    gemm_f16<<<dim3(1024 / 128, M_TOT / 256), 512, GEMM_SMEM_BYTES>>>(
        gAtt, woh, bo, out, nullptr, nullptr, nullptr, 1024, 0);
}

// round 13
// speedup vs baseline: 1.3182x; 1.1666x over previous
#include <cuda_runtime.h>
#include <cuda_fp16.h>
#include <cstdint>

#define BB 4
#define TT 2048
#define CC 1024
#define HH 16
#define DD 64
#define M_TOT (BB*TT)   // 8192

// Scratch (device globals: allocation-free rule)
__device__ __half g_xh[M_TOT*CC];        // x in fp16
__device__ __half g_wqkvh[CC*3*CC];      // W_qkv in fp16 [K][N]
__device__ __half g_woh[CC*CC];          // W_o in fp16 [K][N]
__device__ __half g_Q[BB*HH*TT*DD];      // [B,H,T,D] fp16, pre-scaled by log2(e)/8
__device__ __half g_K[BB*HH*TT*DD];
__device__ __half g_V[BB*HH*TT*DD];
__device__ __half g_Att[M_TOT*CC];       // attention out [B,T,C] fp16

__device__ __forceinline__ void mma_f16(float& c0, float& c1, float& c2, float& c3,
                                        uint32_t a0, uint32_t a1, uint32_t a2, uint32_t a3,
                                        uint32_t b0, uint32_t b1)
{
    asm volatile(
        "mma.sync.aligned.m16n8k16.row.col.f32.f16.f16.f32 "
        "{%0,%1,%2,%3}, {%4,%5,%6,%7}, {%8,%9}, {%0,%1,%2,%3};"
        : "+f"(c0), "+f"(c1), "+f"(c2), "+f"(c3)
        : "r"(a0), "r"(a1), "r"(a2), "r"(a3), "r"(b0), "r"(b1));
}

__device__ __forceinline__ void ldsm_x4(uint32_t& r0, uint32_t& r1, uint32_t& r2, uint32_t& r3,
                                        uint32_t addr)
{
    asm volatile("ldmatrix.sync.aligned.m8n8.x4.shared.b16 {%0,%1,%2,%3}, [%4];"
                 : "=r"(r0), "=r"(r1), "=r"(r2), "=r"(r3) : "r"(addr));
}

__device__ __forceinline__ void ldsm_x4_t(uint32_t& r0, uint32_t& r1, uint32_t& r2, uint32_t& r3,
                                          uint32_t addr)
{
    asm volatile("ldmatrix.sync.aligned.m8n8.x4.trans.shared.b16 {%0,%1,%2,%3}, [%4];"
                 : "=r"(r0), "=r"(r1), "=r"(r2), "=r"(r3) : "r"(addr));
}

__device__ __forceinline__ void cp_async16(void* smem_dst, const void* gmem_src) {
    uint32_t s = (uint32_t)__cvta_generic_to_shared(smem_dst);
    asm volatile("cp.async.cg.shared.global [%0], [%1], 16;" :: "r"(s), "l"(gmem_src));
}
#define CP_COMMIT() asm volatile("cp.async.commit_group;")
#define CP_WAIT1()  asm volatile("cp.async.wait_group 1;")
#define CP_WAIT0()  asm volatile("cp.async.wait_all;")

// pack two f32 -> half2 (lo, hi), then exp2 in fp16x2
__device__ __forceinline__ uint32_t exp2_pack(float lo, float hi) {
    uint32_t t, r;
    asm("cvt.rn.f16x2.f32 %0, %1, %2;" : "=r"(t) : "f"(hi), "f"(lo));
    asm("ex2.approx.f16x2 %0, %1;" : "=r"(r) : "r"(t));
    return r;
}

// ---------------------------------------------------------------------------
// fp32 -> fp16 conversion (one-time preprocess)
// ---------------------------------------------------------------------------
__global__ void cvt_half_kernel(const float* __restrict__ src, __half* __restrict__ dst, int n)
{
    int i = (blockIdx.x * blockDim.x + threadIdx.x) * 4;
    if (i < n) {
        float4 v = *(const float4*)&src[i];
        *(__half2*)&dst[i]     = __floats2half2_rn(v.x, v.y);
        *(__half2*)&dst[i + 2] = __floats2half2_rn(v.z, v.w);
    }
}

// ---------------------------------------------------------------------------
// fp16 GEMM (R9 config): cp.async 3-stage, K-tile 64, tile 128x128,
// 256 threads (8 warps 4m x 2n, warp 32x64), 2 CTA/SM, fp32 accumulate.
// mode 0: fp32 row-major write; mode 1: QKV fp16 scatter (Q pre-scaled).
// ---------------------------------------------------------------------------
#define GA_STH 72
#define GB_STH 136
#define GA_H (128*GA_STH)
#define GB_H (64*GB_STH)
#define GEMM_SMEM_BYTES ((3*GA_H + 3*GB_H) * 2)   // 107520
#define QSCALE 0.1803368801f                       // log2(e)/8

__global__ __launch_bounds__(256, 2)
void gemm_f16(const __half* __restrict__ A, const __half* __restrict__ W,
              const float* __restrict__ bias, float* __restrict__ Out,
              __half* __restrict__ Qp, __half* __restrict__ Kp, __half* __restrict__ Vp,
              int N, int mode)
{
    extern __shared__ __half smh[];
    __half* Asm[3] = { smh, smh + GA_H, smh + 2*GA_H };
    __half* Bsm[3] = { smh + 3*GA_H, smh + 3*GA_H + GB_H, smh + 3*GA_H + 2*GB_H };

    const int tid  = threadIdx.x;
    const int wid  = tid >> 5;
    const int lane = tid & 31;
    const int g    = lane >> 2;
    const int tig  = lane & 3;
    const int lr   = lane & 7;
    const int sel  = lane >> 3;
    const int wm   = wid & 3;
    const int wn   = wid >> 2;
    const int n0   = blockIdx.x * 128;
    const int m0   = blockIdx.y * 128;

    uint32_t smA[3], smB[3];
#pragma unroll
    for (int i = 0; i < 3; ++i) {
        smA[i] = (uint32_t)__cvta_generic_to_shared(Asm[i]);
        smB[i] = (uint32_t)__cvta_generic_to_shared(Bsm[i]);
    }
    const uint32_t aOff = ((wm * 32 + (sel & 1) * 8 + lr) * GA_STH + (sel >> 1) * 8) * 2;
    const uint32_t bOff = (((sel & 1) * 8 + lr) * GB_STH + wn * 64 + (sel >> 1) * 8) * 2;

    float acc[2][8][4];
#pragma unroll
    for (int mt = 0; mt < 2; ++mt)
#pragma unroll
        for (int nt = 0; nt < 8; ++nt)
#pragma unroll
            for (int q = 0; q < 4; ++q) acc[mt][nt][q] = 0.f;

    auto prefetch = [&](int s, int buf) {
        const int k0 = s * 64;
#pragma unroll
        for (int p = 0; p < 4; ++p) {
            int c  = tid + p * 256;
            int ra = c >> 3;
            int ka = (c & 7) * 8;
            cp_async16(&Asm[buf][ra * GA_STH + ka], &A[(m0 + ra) * 1024 + k0 + ka]);
            int rb = c >> 4;
            int nb = (c & 15) * 8;
            cp_async16(&Bsm[buf][rb * GB_STH + nb], &W[(k0 + rb) * N + n0 + nb]);
        }
    };

    prefetch(0, 0); CP_COMMIT();
    prefetch(1, 1); CP_COMMIT();

    for (int s = 0; s < 16; ++s) {
        CP_WAIT1();
        __syncthreads();
        if (s + 2 < 16) prefetch(s + 2, (s + 2) % 3);
        CP_COMMIT();

        const int buf = s % 3;
#pragma unroll
        for (int ks = 0; ks < 4; ++ks) {
            uint32_t a[2][4];
#pragma unroll
            for (int mt = 0; mt < 2; ++mt)
                ldsm_x4(a[mt][0], a[mt][1], a[mt][2], a[mt][3],
                        smA[buf] + aOff + (mt * 16 * GA_STH + ks * 16) * 2);
#pragma unroll
            for (int ph = 0; ph < 2; ++ph) {
                uint32_t b0[4], b1[4];
                ldsm_x4_t(b0[0], b0[1], b0[2], b0[3],
                          smB[buf] + bOff + (ks * 16 * GB_STH + (ph * 2 + 0) * 16) * 2);
                ldsm_x4_t(b1[0], b1[1], b1[2], b1[3],
                          smB[buf] + bOff + (ks * 16 * GB_STH + (ph * 2 + 1) * 16) * 2);
#pragma unroll
                for (int mt = 0; mt < 2; ++mt) {
                    mma_f16(acc[mt][4*ph+0][0], acc[mt][4*ph+0][1], acc[mt][4*ph+0][2], acc[mt][4*ph+0][3],
                            a[mt][0], a[mt][1], a[mt][2], a[mt][3], b0[0], b0[1]);
                    mma_f16(acc[mt][4*ph+1][0], acc[mt][4*ph+1][1], acc[mt][4*ph+1][2], acc[mt][4*ph+1][3],
                            a[mt][0], a[mt][1], a[mt][2], a[mt][3], b0[2], b0[3]);
                    mma_f16(acc[mt][4*ph+2][0], acc[mt][4*ph+2][1], acc[mt][4*ph+2][2], acc[mt][4*ph+2][3],
                            a[mt][0], a[mt][1], a[mt][2], a[mt][3], b1[0], b1[1]);
                    mma_f16(acc[mt][4*ph+3][0], acc[mt][4*ph+3][1], acc[mt][4*ph+3][2], acc[mt][4*ph+3][3],
                            a[mt][0], a[mt][1], a[mt][2], a[mt][3], b1[2], b1[3]);
                }
            }
        }
    }

    // epilogue (Q columns pre-scaled by QSCALE for the attention exp2 domain)
#pragma unroll
    for (int mt = 0; mt < 2; ++mt) {
#pragma unroll
        for (int nt = 0; nt < 8; ++nt) {
            int col = n0 + wn * 64 + nt * 8 + tig * 2;
            float2 bv = *(const float2*)&bias[col];
            int r0 = m0 + wm * 32 + mt * 16 + g;
#pragma unroll
            for (int h = 0; h < 2; ++h) {
                int row = r0 + h * 8;
                float vx = acc[mt][nt][h * 2 + 0] + bv.x;
                float vy = acc[mt][nt][h * 2 + 1] + bv.y;
                if (mode == 0) {
                    float2 v; v.x = vx; v.y = vy;
                    *(float2*)&Out[row * N + col] = v;
                } else {
                    int sec = col >> 10;           // 0:Q 1:K 2:V
                    if (sec == 0) { vx *= QSCALE; vy *= QSCALE; }
                    int rem = col & 1023;
                    int hh  = rem >> 6;
                    int d   = rem & 63;
                    int b   = row >> 11;
                    int t   = row & 2047;
                    __half* dst = (sec == 0) ? Qp : (sec == 1) ? Kp : Vp;
                    *(__half2*)&dst[(((b * HH + hh) * TT + t) << 6) + d] =
                        __floats2half2_rn(vx, vy);
                }
            }
        }
    }
}

// ---------------------------------------------------------------------------
// Flash attention: R9 inner loop (static-max exp2/fp16 softmax, mma row-sums,
// 3-stage KV pipeline) with a snake-balanced 296-CTA persistent grid.
// Work units u in [0,1024): qb = 15 - u/64 (cost-descending), bh = u % 64.
// CTA bid processes u_r = r*296 + (r odd ? 295-bid : bid), r = 0..3.
// Per-CTA load: 58-60 KV tiles (ideal 58.8) -> one balanced wave.
// ---------------------------------------------------------------------------
#define KV_STH 72
#define KV_H (64*KV_STH)
#define ATTN_SMEM_BYTES (6*KV_H*2)              // 55296
#define MASKV (-30.0f)
#define ATTN_GRID 296

__global__ __launch_bounds__(256, 2)
void attn_f16(const __half* __restrict__ Q, const __half* __restrict__ K,
              const __half* __restrict__ V, __half* __restrict__ O)
{
    extern __shared__ __half smh[];
    __half* Kb[3] = { smh,        smh + 2*KV_H, smh + 4*KV_H };
    __half* Vb[3] = { smh + KV_H, smh + 3*KV_H, smh + 5*KV_H };

    const int tid  = threadIdx.x;
    const int wid  = tid >> 5;
    const int lane = tid & 31;
    const int g    = lane >> 2;
    const int tig  = lane & 3;
    const int lr   = lane & 7;
    const int sel  = lane >> 3;
    const int wq   = wid * 16;
    const int bid  = blockIdx.x;

    uint32_t smK[3], smV[3];
#pragma unroll
    for (int i = 0; i < 3; ++i) {
        smK[i] = (uint32_t)__cvta_generic_to_shared(Kb[i]);
        smV[i] = (uint32_t)__cvta_generic_to_shared(Vb[i]);
    }
    const uint32_t kOff = (((sel >> 1) * 8 + lr) * KV_STH + (sel & 1) * 8) * 2;
    const uint32_t vOff = (((sel & 1) * 8 + lr) * KV_STH + (sel >> 1) * 8) * 2;
    const uint32_t qOff = ((wq + (sel & 1) * 8 + lr) * KV_STH + (sel >> 1) * 8) * 2;

    const uint32_t onesb = ((lane >> 2) == 0) ? 0x3C003C00u : 0u;

#pragma unroll 1
    for (int r = 0; r < 4; ++r) {
        const int u = r * ATTN_GRID + ((r & 1) ? (ATTN_GRID - 1 - bid) : bid);
        if (u >= 1024) continue;
        const int qb = 15 - (u >> 6);     // cost-descending
        const int bh = u & 63;
        const int q0 = qb * 128;

        const int base = bh * TT * DD;
        const __half* Qg = Q + base;
        const __half* Kg = K + base;
        const __half* Vg = V + base;

        CP_WAIT0();
        __syncthreads();
        // stage Q (already pre-scaled in QKV epilogue)
#pragma unroll
        for (int p = 0; p < 16; ++p) {
            int idx = tid + p * 256;
            int rr  = idx >> 5;
            int d2  = (idx & 31);
            *(__half2*)&smh[rr * KV_STH + d2 * 2] =
                *(const __half2*)&Qg[(q0 + rr) * DD + d2 * 2];
        }
        __syncthreads();

        uint32_t qa[4][4];
        {
            uint32_t qBase = (uint32_t)__cvta_generic_to_shared(smh);
#pragma unroll
            for (int ks = 0; ks < 4; ++ks)
                ldsm_x4(qa[ks][0], qa[ks][1], qa[ks][2], qa[ks][3],
                        qBase + qOff + ks * 32);
            __syncthreads();   // Q reads done before K/V cp.async overwrites
        }

        float o[8][4];
#pragma unroll
        for (int nt = 0; nt < 8; ++nt)
#pragma unroll
            for (int q = 0; q < 4; ++q) o[nt][q] = 0.f;
        float lsum[4] = {0.f, 0.f, 0.f, 0.f};

        const int row0 = q0 + wq + g;
        const int row1 = row0 + 8;
        const int n_tiles = 2 * (qb + 1);

        auto prefetch = [&](int jt, int buf) {
            const int k0 = jt * 64;
#pragma unroll
            for (int p = 0; p < 2; ++p) {
                int c  = tid + p * 256;
                int rr = c >> 3;
                int dc = (c & 7) * 8;
                cp_async16(&Kb[buf][rr * KV_STH + dc], &Kg[(k0 + rr) * DD + dc]);
                cp_async16(&Vb[buf][rr * KV_STH + dc], &Vg[(k0 + rr) * DD + dc]);
            }
        };

        prefetch(0, 0); CP_COMMIT();
        prefetch(1, 1); CP_COMMIT();

        for (int jt = 0; jt < n_tiles; ++jt) {
            const int k0 = jt * 64;
            CP_WAIT1();
            __syncthreads();
            if (jt + 2 < n_tiles) prefetch(jt + 2, (jt + 2) % 3);
            CP_COMMIT();

            const int buf = jt % 3;

            float sc[8][4];
#pragma unroll
            for (int nt = 0; nt < 8; ++nt)
#pragma unroll
                for (int q = 0; q < 4; ++q) sc[nt][q] = 0.f;

#pragma unroll
            for (int ks = 0; ks < 4; ++ks) {
#pragma unroll
                for (int ph = 0; ph < 2; ++ph) {
                    uint32_t b0[4], b1[4];
                    ldsm_x4(b0[0], b0[1], b0[2], b0[3],
                            smK[buf] + kOff + ((ph * 2 + 0) * 16 * KV_STH + ks * 16) * 2);
                    ldsm_x4(b1[0], b1[1], b1[2], b1[3],
                            smK[buf] + kOff + ((ph * 2 + 1) * 16 * KV_STH + ks * 16) * 2);
                    mma_f16(sc[4*ph+0][0], sc[4*ph+0][1], sc[4*ph+0][2], sc[4*ph+0][3],
                            qa[ks][0], qa[ks][1], qa[ks][2], qa[ks][3], b0[0], b0[1]);
                    mma_f16(sc[4*ph+1][0], sc[4*ph+1][1], sc[4*ph+1][2], sc[4*ph+1][3],
                            qa[ks][0], qa[ks][1], qa[ks][2], qa[ks][3], b0[2], b0[3]);
                    mma_f16(sc[4*ph+2][0], sc[4*ph+2][1], sc[4*ph+2][2], sc[4*ph+2][3],
                            qa[ks][0], qa[ks][1], qa[ks][2], qa[ks][3], b1[0], b1[1]);
                    mma_f16(sc[4*ph+3][0], sc[4*ph+3][1], sc[4*ph+3][2], sc[4*ph+3][3],
                            qa[ks][0], qa[ks][1], qa[ks][2], qa[ks][3], b1[2], b1[3]);
                }
            }

            if (k0 + 63 > row0) {
#pragma unroll
                for (int nt = 0; nt < 8; ++nt) {
                    int c0 = k0 + nt * 8 + tig * 2;
                    int c1 = c0 + 1;
                    if (c0 > row0) sc[nt][0] = MASKV;
                    if (c1 > row0) sc[nt][1] = MASKV;
                    if (c0 > row1) sc[nt][2] = MASKV;
                    if (c1 > row1) sc[nt][3] = MASKV;
                }
            }

            uint32_t ph16[8][2];
#pragma unroll
            for (int nt = 0; nt < 8; ++nt) {
                ph16[nt][0] = exp2_pack(sc[nt][0], sc[nt][1]);
                ph16[nt][1] = exp2_pack(sc[nt][2], sc[nt][3]);
            }

#pragma unroll
            for (int c = 0; c < 4; ++c) {
                uint32_t a0 = ph16[2*c    ][0];
                uint32_t a1 = ph16[2*c    ][1];
                uint32_t a2 = ph16[2*c + 1][0];
                uint32_t a3 = ph16[2*c + 1][1];
                mma_f16(lsum[0], lsum[1], lsum[2], lsum[3],
                        a0, a1, a2, a3, onesb, onesb);
#pragma unroll
                for (int ph = 0; ph < 2; ++ph) {
                    uint32_t b0[4], b1[4];
                    ldsm_x4_t(b0[0], b0[1], b0[2], b0[3],
                              smV[buf] + vOff + (c * 16 * KV_STH + (ph * 2 + 0) * 16) * 2);
                    ldsm_x4_t(b1[0], b1[1], b1[2], b1[3],
                              smV[buf] + vOff + (c * 16 * KV_STH + (ph * 2 + 1) * 16) * 2);
                    mma_f16(o[4*ph+0][0], o[4*ph+0][1], o[4*ph+0][2], o[4*ph+0][3],
                            a0, a1, a2, a3, b0[0], b0[1]);
                    mma_f16(o[4*ph+1][0], o[4*ph+1][1], o[4*ph+1][2], o[4*ph+1][3],
                            a0, a1, a2, a3, b0[2], b0[3]);
                    mma_f16(o[4*ph+2][0], o[4*ph+2][1], o[4*ph+2][2], o[4*ph+2][3],
                            a0, a1, a2, a3, b1[0], b1[1]);
                    mma_f16(o[4*ph+3][0], o[4*ph+3][1], o[4*ph+3][2], o[4*ph+3][3],
                            a0, a1, a2, a3, b1[2], b1[3]);
                }
            }
        }

        int qlead = lane & ~3;
        float l0 = __shfl_sync(0xffffffffu, lsum[0], qlead);
        float l1 = __shfl_sync(0xffffffffu, lsum[2], qlead);
        float inv0 = 1.f / l0;
        float inv1 = 1.f / l1;
        const int b    = bh >> 4;
        const int head = bh & 15;
#pragma unroll
        for (int nt = 0; nt < 8; ++nt) {
            int d = head * DD + nt * 8 + tig * 2;
            *(__half2*)&O[(b * TT + row0) * CC + d] =
                __floats2half2_rn(o[nt][0] * inv0, o[nt][1] * inv0);
            *(__half2*)&O[(b * TT + row1) * CC + d] =
                __floats2half2_rn(o[nt][2] * inv1, o[nt][3] * inv1);
        }
    }
}

// ---------------------------------------------------------------------------
extern "C" void kernel_launch(void* const* d_in, const int* in_sizes, int n_in,
                              void* d_out, int out_size)
{
    const float* x    = (const float*)d_in[0];  // [4,2048,1024]
    const float* Wqkv = (const float*)d_in[1];  // [1024,3072]
    const float* bqkv = (const float*)d_in[2];  // [3072]
    const float* Wo   = (const float*)d_in[3];  // [1024,1024]
    const float* bo   = (const float*)d_in[4];  // [1024]
    float* out = (float*)d_out;                 // [4,2048,1024]

    __half *xh, *wqkvh, *woh, *gQ, *gK, *gV, *gAtt;
    cudaGetSymbolAddress((void**)&xh,    g_xh);
    cudaGetSymbolAddress((void**)&wqkvh, g_wqkvh);
    cudaGetSymbolAddress((void**)&woh,   g_woh);
    cudaGetSymbolAddress((void**)&gQ,    g_Q);
    cudaGetSymbolAddress((void**)&gK,    g_K);
    cudaGetSymbolAddress((void**)&gV,    g_V);
    cudaGetSymbolAddress((void**)&gAtt,  g_Att);

    cudaFuncSetAttribute(gemm_f16, cudaFuncAttributeMaxDynamicSharedMemorySize,
                         GEMM_SMEM_BYTES);
    cudaFuncSetAttribute(attn_f16, cudaFuncAttributeMaxDynamicSharedMemorySize,
                         ATTN_SMEM_BYTES);

    // 0) convert inputs to fp16
    cvt_half_kernel<<<(M_TOT*CC/4 + 255)/256, 256>>>(x, xh, M_TOT*CC);
    cvt_half_kernel<<<(CC*3*CC/4 + 255)/256, 256>>>(Wqkv, wqkvh, CC*3*CC);
    cvt_half_kernel<<<(CC*CC/4 + 255)/256, 256>>>(Wo, woh, CC*CC);

    // 1) QKV projection + fp16 scatter to [B,H,T,D] (Q pre-scaled)
    gemm_f16<<<dim3(3072 / 128, M_TOT / 128), 256, GEMM_SMEM_BYTES>>>(
        xh, wqkvh, bqkv, nullptr, gQ, gK, gV, 3072, 1);

    // 2) causal flash attention -> fp16 [B,T,C] (snake-balanced 296-CTA grid)
    attn_f16<<<ATTN_GRID, 256, ATTN_SMEM_BYTES>>>(gQ, gK, gV, gAtt);

    // 3) output projection (fp16 in, fp32 out)
    gemm_f16<<<dim3(1024 / 128, M_TOT / 128), 256, GEMM_SMEM_BYTES>>>(
        gAtt, woh, bo, out, nullptr, nullptr, nullptr, 1024, 0);
}